// round 5
// baseline (speedup 1.0000x reference)
#include <cuda_runtime.h>
#include <cuda_bf16.h>
#include <cstdint>

// Problem constants
#define BB   4
#define CC   150
#define CP   160          // padded channels (for GEMM tiles of 16)
#define HH   320
#define WW   320
#define HWX  (HH*WW)      // 102400
#define KTAP 7
#define PADR 3
#define KP   168          // smem K stride (bf16 elems), padded for bank-conflict-free frags

// ---------------- scratch (static device memory; no cudaMalloc allowed) ---------------
__device__ __nv_bfloat16 g_comp[CP * CP];                       // sigmoid(100*compat), bf16, zero-padded
__device__ __nv_bfloat16 g_E[(size_t)BB * CP * HWX];            // exp(logit), bf16, channel-padded w/ zeros
__device__ float         g_R[(size_t)BB * CP * HWX];            // R = comp @ softmax(logit)
__device__ float         g_invs[(size_t)BB * HWX];              // 1 / sum_c exp(logit)

// ---------------- K0: compatibility -> sigmoid -> bf16 (padded) ----------------------
__global__ void k0_comp(const float* __restrict__ compat) {
    int t = blockIdx.x * blockDim.x + threadIdx.x;
    if (t >= CP * CP) return;
    int o = t / CP, i = t - o * CP;
    float v = 0.f;
    if (o < CC && i < CC) {
        float x = 100.0f * compat[o * CC + i];
        v = 1.0f / (1.0f + __expf(-x));
    }
    g_comp[t] = __float2bfloat16(v);
}

// ---------------- K1: per-pixel exp + 1/sum (softmax split) --------------------------
__global__ void k1_softmax(const float* __restrict__ logit) {
    int t = blockIdx.x * blockDim.x + threadIdx.x;
    if (t >= BB * HWX) return;
    int b = t / HWX, n = t - b * HWX;
    const float* src = logit + (size_t)b * CC * HWX + n;
    __nv_bfloat16* dst = g_E + (size_t)b * CP * HWX + n;
    float s = 0.f;
    for (int c = 0; c < CC; c++) {
        float e = __expf(src[(size_t)c * HWX]);
        s += e;
        dst[(size_t)c * HWX] = __float2bfloat16(e);
    }
    // zero the channel padding so padded K rows contribute nothing in the GEMM
    #pragma unroll
    for (int c = CC; c < CP; c++) dst[(size_t)c * HWX] = __float2bfloat16(0.f);
    g_invs[t] = 1.0f / s;
}

// ---------------- K2: GEMM  R[b,o,n] = invs[b,n] * sum_k comp[o,k] * E[b,k,n] --------
// mma.sync m16n8k16 bf16, fp32 accumulate.
// Block: 256 threads, tile M=160 (all outputs), N=128. K loop over 160.
__device__ __forceinline__ void mma16816(float* c,
                                         uint32_t a0, uint32_t a1, uint32_t a2, uint32_t a3,
                                         uint32_t b0, uint32_t b1) {
    asm volatile(
        "mma.sync.aligned.m16n8k16.row.col.f32.bf16.bf16.f32 "
        "{%0,%1,%2,%3}, {%4,%5,%6,%7}, {%8,%9}, {%0,%1,%2,%3};\n"
        : "+f"(c[0]), "+f"(c[1]), "+f"(c[2]), "+f"(c[3])
        : "r"(a0), "r"(a1), "r"(a2), "r"(a3), "r"(b0), "r"(b1));
}

#define SMEM_K2 ((CP * KP + 128 * KP) * 2)   // 96768 bytes

__global__ __launch_bounds__(256) void k2_gemm() {
    extern __shared__ __nv_bfloat16 sm[];
    __nv_bfloat16* sA = sm;                 // [CP][KP]  comp, row-major (m,k)
    __nv_bfloat16* sB = sm + CP * KP;       // [128][KP] E transposed: (n, k)

    int b  = blockIdx.y;
    int n0 = blockIdx.x * 128;
    int tid = threadIdx.x;

    // load A (comp) : 25600 elems
    for (int idx = tid; idx < CP * CP; idx += 256) {
        int m = idx / CP, k = idx - m * CP;
        sA[m * KP + k] = g_comp[idx];
    }
    // load B transposed: sB[nn][k] = E[b][k][n0+nn]
    const __nv_bfloat16* Eb = g_E + (size_t)b * CP * HWX + n0;
    for (int idx = tid; idx < CP * 128; idx += 256) {
        int k = idx >> 7, nn = idx & 127;
        sB[nn * KP + k] = Eb[(size_t)k * HWX + nn];
    }
    __syncthreads();

    int warp = tid >> 5, lane = tid & 31;
    int gid = lane >> 2, tig = lane & 3;
    int nt0 = warp * 2;          // this warp owns n8-tiles nt0, nt0+1

    float acc[10][2][4];
    #pragma unroll
    for (int mt = 0; mt < 10; mt++)
        #pragma unroll
        for (int nt = 0; nt < 2; nt++)
            #pragma unroll
            for (int q = 0; q < 4; q++) acc[mt][nt][q] = 0.f;

    #pragma unroll
    for (int k0 = 0; k0 < CP; k0 += 16) {
        uint32_t bf[2][2];
        #pragma unroll
        for (int nt = 0; nt < 2; nt++) {
            int n = (nt0 + nt) * 8 + gid;
            const uint32_t* p = (const uint32_t*)&sB[n * KP + k0];
            bf[nt][0] = p[tig];
            bf[nt][1] = p[tig + 4];
        }
        #pragma unroll
        for (int mt = 0; mt < 10; mt++) {
            int m = mt * 16 + gid;
            const uint32_t* pa0 = (const uint32_t*)&sA[m * KP + k0];
            const uint32_t* pa1 = (const uint32_t*)&sA[(m + 8) * KP + k0];
            uint32_t a0 = pa0[tig], a1 = pa1[tig], a2 = pa0[tig + 4], a3 = pa1[tig + 4];
            #pragma unroll
            for (int nt = 0; nt < 2; nt++)
                mma16816(acc[mt][nt], a0, a1, a2, a3, bf[nt][0], bf[nt][1]);
        }
    }

    // epilogue: scale columns by invs, store R (channels-first)
    const float* invs = g_invs + (size_t)b * HWX + n0;
    float* Rb = g_R + (size_t)b * CP * HWX + n0;
    #pragma unroll
    for (int nt = 0; nt < 2; nt++) {
        int col = (nt0 + nt) * 8 + 2 * tig;
        float s0 = invs[col], s1 = invs[col + 1];
        #pragma unroll
        for (int mt = 0; mt < 10; mt++) {
            int row = mt * 16 + gid;
            float2 v0 = make_float2(acc[mt][nt][0] * s0, acc[mt][nt][1] * s1);
            float2 v1 = make_float2(acc[mt][nt][2] * s0, acc[mt][nt][3] * s1);
            *(float2*)&Rb[(size_t)row * HWX + col]       = v0;
            *(float2*)&Rb[(size_t)(row + 8) * HWX + col] = v1;
        }
    }
}

// ---------------- K3: out = logit - CRF(F, R) ---------------------------------------
// Block: 256 threads, spatial tile 32x32 (thread = 1 row x 4 cols), channels 4 at a time
// in a shared halo tile. F stays L1-resident (per-block working set ~200KB, reread
// 38x from L1); R loaded with .cg to keep it out of L1.
#define HALO 38
#define SRP  41            // padded row stride (odd -> conflict-free window reads)

__global__ __launch_bounds__(256) void k3_crf(const float* __restrict__ inF,
                                              const float* __restrict__ logit,
                                              float* __restrict__ out) {
    __shared__ float sR[4][HALO * SRP];

    int b   = blockIdx.z;
    int gx0 = blockIdx.x * 32;
    int gy0 = blockIdx.y * 32;
    int tid = threadIdx.x;
    int tx  = tid & 7;          // 8 thread-cols * 4 px = 32 wide
    int ty  = tid >> 3;         // 32 rows
    int ox  = gx0 + 4 * tx;
    int oy  = gy0 + ty;

    const float* Fbase = inF + (size_t)b * (KTAP * KTAP) * HWX + (size_t)oy * WW + ox;
    const float* Rb    = g_R + (size_t)b * CP * HWX;

    for (int c0 = 0; c0 < CC; c0 += 4) {
        __syncthreads();   // previous iteration's reads done before refill
        // cooperative halo load: 4 channels x 38 x 38 (zero padded at borders)
        for (int idx = tid; idx < 4 * HALO * HALO; idx += 256) {
            int ch = idx / (HALO * HALO);
            int r  = idx - ch * (HALO * HALO);
            int rr = r / HALO;
            int cc2 = r - rr * HALO;
            int gr = gy0 + rr - PADR, gc = gx0 + cc2 - PADR;
            int c = c0 + ch;
            float v = 0.f;
            if (c < CC && (unsigned)gr < (unsigned)HH && (unsigned)gc < (unsigned)WW)
                v = __ldcg(&Rb[(size_t)c * HWX + (size_t)gr * WW + gc]);
            sR[ch][rr * SRP + cc2] = v;
        }
        __syncthreads();

        float acc[4][4];   // [px][ch]
        #pragma unroll
        for (int px = 0; px < 4; px++)
            #pragma unroll
            for (int ch = 0; ch < 4; ch++) acc[px][ch] = 0.f;

        #pragma unroll
        for (int di = 0; di < KTAP; di++) {
            // 10-col sliding window per channel (output cols ox..ox+3, taps dj 0..6)
            float rw[4][10];
            int rbase = (ty + di) * SRP + 4 * tx;
            #pragma unroll
            for (int ch = 0; ch < 4; ch++)
                #pragma unroll
                for (int q = 0; q < 10; q++) rw[ch][q] = sR[ch][rbase + q];

            #pragma unroll
            for (int dj = 0; dj < KTAP; dj++) {
                float4 f = *(const float4*)(Fbase + (size_t)(di * KTAP + dj) * HWX);
                #pragma unroll
                for (int ch = 0; ch < 4; ch++) {
                    acc[0][ch] += f.x * rw[ch][dj];
                    acc[1][ch] += f.y * rw[ch][dj + 1];
                    acc[2][ch] += f.z * rw[ch][dj + 2];
                    acc[3][ch] += f.w * rw[ch][dj + 3];
                }
            }
        }

        #pragma unroll
        for (int ch = 0; ch < 4; ch++) {
            int c = c0 + ch;
            if (c >= CC) break;
            size_t o = ((size_t)b * CC + c) * HWX + (size_t)oy * WW + ox;
            float4 lg = *(const float4*)(logit + o);
            float4 r;
            r.x = lg.x - acc[0][ch];
            r.y = lg.y - acc[1][ch];
            r.z = lg.z - acc[2][ch];
            r.w = lg.w - acc[3][ch];
            *(float4*)(out + o) = r;
        }
    }
}

// ---------------- launch --------------------------------------------------------------
extern "C" void kernel_launch(void* const* d_in, const int* in_sizes, int n_in,
                              void* d_out, int out_size) {
    const float* F      = (const float*)d_in[0];   // [B, 49, H, W]
    const float* logit  = (const float*)d_in[1];   // [B, C, H, W]
    const float* compat = (const float*)d_in[2];   // [C, C, 1, 1]
    float* out = (float*)d_out;

    cudaFuncSetAttribute(k2_gemm, cudaFuncAttributeMaxDynamicSharedMemorySize, SMEM_K2);

    k0_comp<<<(CP * CP + 255) / 256, 256>>>(compat);
    k1_softmax<<<(BB * HWX) / 256, 256>>>(logit);
    k2_gemm<<<dim3(HWX / 128, BB), 256, SMEM_K2>>>();
    k3_crf<<<dim3(WW / 32, HH / 32, BB), 256>>>(F, logit, out);
}

// round 6
// speedup vs baseline: 1.1540x; 1.1540x over previous
#include <cuda_runtime.h>
#include <cuda_bf16.h>
#include <cstdint>

// Problem constants
#define BB   4
#define CC   150
#define CP   160          // padded channels (GEMM tiles of 16); row CC holds the ones-row (sum)
#define HH   320
#define WW   320
#define HWX  (HH*WW)      // 102400
#define KP   168          // k2 smem K stride (bf16 elems), conflict-free

// ---------------- scratch (static device memory) -------------------------------------
__device__ __nv_bfloat16 g_comp[CP * CP];              // sigmoid(100*compat), bf16; row 150 = ones
__device__ float         g_R[(size_t)BB * CP * HWX];   // normalized R; rows 150..151 zeroed

// ---------------- K0: compatibility -> sigmoid -> bf16 (+ ones row) -------------------
__global__ void k0_comp(const float* __restrict__ compat) {
    int t = blockIdx.x * blockDim.x + threadIdx.x;
    if (t >= CP * CP) return;
    int o = t / CP, i = t - o * CP;
    float v = 0.f;
    if (i < CC) {
        if (o < CC) {
            float x = 100.0f * compat[o * CC + i];
            v = 1.0f / (1.0f + __expf(-x));
        } else if (o == CC) {
            v = 1.0f;                    // sum row
        }
    }
    g_comp[t] = __float2bfloat16(v);
}

// ---------------- K2: fused softmax + GEMM -------------------------------------------
// R[b,o,n] = (sum_k comp[o,k] * exp(logit[b,k,n])) / (sum_k exp(logit[b,k,n]))
// mma.sync m16n8k16 bf16 fp32-acc. Block: 256 thr, M=160 (row 150 = sums), N=128.
__device__ __forceinline__ void mma16816(float* c,
                                         uint32_t a0, uint32_t a1, uint32_t a2, uint32_t a3,
                                         uint32_t b0, uint32_t b1) {
    asm volatile(
        "mma.sync.aligned.m16n8k16.row.col.f32.bf16.bf16.f32 "
        "{%0,%1,%2,%3}, {%4,%5,%6,%7}, {%8,%9}, {%0,%1,%2,%3};\n"
        : "+f"(c[0]), "+f"(c[1]), "+f"(c[2]), "+f"(c[3])
        : "r"(a0), "r"(a1), "r"(a2), "r"(a3), "r"(b0), "r"(b1));
}

#define SMEM_K2 ((CP * KP + 128 * KP) * 2)   // 96768 bytes

__global__ __launch_bounds__(256) void k2_gemm(const float* __restrict__ logit) {
    extern __shared__ __nv_bfloat16 sm[];
    __nv_bfloat16* sA = sm;                 // [CP][KP]  comp, row-major (m,k)
    __nv_bfloat16* sB = sm + CP * KP;       // [128][KP] exp(logit) transposed: (n, k)

    int b  = blockIdx.y;
    int n0 = blockIdx.x * 128;
    int tid = threadIdx.x;

    // load A (comp)
    for (int idx = tid; idx < CP * CP; idx += 256) {
        int m = idx / CP, k = idx - m * CP;
        sA[m * KP + k] = g_comp[idx];
    }
    // B fill with fused exp: each thread produces 8 consecutive k for one nn -> STS.128
    const float* Lb = logit + (size_t)b * CC * HWX + n0;
    for (int t = tid; t < 20 * 128; t += 256) {
        int ko = t >> 7, nn = t & 127;
        int kb = ko * 8;
        float e[8];
        #pragma unroll
        for (int j = 0; j < 8; j++) {
            int kk = kb + j;
            e[j] = (kk < CC) ? __expf(Lb[(size_t)kk * HWX + nn]) : 0.f;
        }
        __nv_bfloat162 p0 = __floats2bfloat162_rn(e[0], e[1]);
        __nv_bfloat162 p1 = __floats2bfloat162_rn(e[2], e[3]);
        __nv_bfloat162 p2 = __floats2bfloat162_rn(e[4], e[5]);
        __nv_bfloat162 p3 = __floats2bfloat162_rn(e[6], e[7]);
        uint4 pk;
        pk.x = *reinterpret_cast<uint32_t*>(&p0);
        pk.y = *reinterpret_cast<uint32_t*>(&p1);
        pk.z = *reinterpret_cast<uint32_t*>(&p2);
        pk.w = *reinterpret_cast<uint32_t*>(&p3);
        *(uint4*)&sB[nn * KP + kb] = pk;
    }
    __syncthreads();

    int warp = tid >> 5, lane = tid & 31;
    int gid = lane >> 2, tig = lane & 3;
    int nt0 = warp * 2;

    float acc[10][2][4];
    #pragma unroll
    for (int mt = 0; mt < 10; mt++)
        #pragma unroll
        for (int nt = 0; nt < 2; nt++)
            #pragma unroll
            for (int q = 0; q < 4; q++) acc[mt][nt][q] = 0.f;

    #pragma unroll
    for (int k0 = 0; k0 < CP; k0 += 16) {
        uint32_t bf[2][2];
        #pragma unroll
        for (int nt = 0; nt < 2; nt++) {
            int n = (nt0 + nt) * 8 + gid;
            const uint32_t* p = (const uint32_t*)&sB[n * KP + k0];
            bf[nt][0] = p[tig];
            bf[nt][1] = p[tig + 4];
        }
        #pragma unroll
        for (int mt = 0; mt < 10; mt++) {
            int m = mt * 16 + gid;
            const uint32_t* pa0 = (const uint32_t*)&sA[m * KP + k0];
            const uint32_t* pa1 = (const uint32_t*)&sA[(m + 8) * KP + k0];
            uint32_t a0 = pa0[tig], a1 = pa1[tig], a2 = pa0[tig + 4], a3 = pa1[tig + 4];
            #pragma unroll
            for (int nt = 0; nt < 2; nt++)
                mma16816(acc[mt][nt], a0, a1, a2, a3, bf[nt][0], bf[nt][1]);
        }
    }

    // epilogue: recover per-column sums from row 150 via shfl, normalize, store
    float* Rb = g_R + (size_t)b * CP * HWX + n0;
    #pragma unroll
    for (int nt = 0; nt < 2; nt++) {
        // lane 24+tig (gid=6) holds row 150 for columns 2tig, 2tig+1 in acc[9][nt][0..1]
        float s0 = __shfl_sync(0xffffffffu, acc[9][nt][0], 24 + tig);
        float s1 = __shfl_sync(0xffffffffu, acc[9][nt][1], 24 + tig);
        float i0 = 1.0f / s0, i1 = 1.0f / s1;
        int col = (nt0 + nt) * 8 + 2 * tig;
        #pragma unroll
        for (int mt = 0; mt < 10; mt++) {
            int row = mt * 16 + gid;
            float v0 = (row < CC) ? acc[mt][nt][0] * i0 : 0.f;   // rows 150..151 -> 0
            float v1 = (row < CC) ? acc[mt][nt][1] * i1 : 0.f;
            *(float2*)&Rb[(size_t)row * HWX + col] = make_float2(v0, v1);
            if (mt < 9) {   // rows 152..159 never read -> skip
                *(float2*)&Rb[(size_t)(row + 8) * HWX + col] =
                    make_float2(acc[mt][nt][2] * i0, acc[mt][nt][3] * i1);
            }
        }
    }
}

// ---------------- K3: out = logit - CRF(F, R) ---------------------------------------
// 256 thr, 32x32 tile, thread = 4px x 8ch. F staged in smem (bf16, read from DRAM once).
// R halo double-buffered via cp.async zfill. Inner product uses packed fma.rn.f32x2.
#define HALO  38
#define SRP   42                  // even -> float2-aligned window loads
#define SRCH  (HALO * SRP)        // 1596 floats per channel
#define SRBUF (8 * SRCH)          // 12768 floats per buffer
#define NGRP  19                  // 19 groups x 8 ch = 152 >= 150
#define K3_SMEM (49 * 1024 * 2 + 2 * SRBUF * 4)   // 100352 + 102144 = 202496 B

__device__ __forceinline__ void FMA2(float2& d, const float2& a, const float2& b) {
    asm("fma.rn.f32x2 %0, %1, %2, %0;"
        : "+l"(reinterpret_cast<unsigned long long&>(d))
        : "l"(reinterpret_cast<const unsigned long long&>(a)),
          "l"(reinterpret_cast<const unsigned long long&>(b)));
}

__device__ __forceinline__ void cpa4(float* dst, const float* src, int sz) {
    unsigned d = (unsigned)__cvta_generic_to_shared(dst);
    asm volatile("cp.async.ca.shared.global [%0], [%1], 4, %2;"
                 :: "r"(d), "l"(src), "r"(sz) : "memory");
}

__device__ __forceinline__ void prefetch_group(float* dst, const float* Rg,
                                               int gx0, int gy0, int tid,
                                               const float* safe) {
    #pragma unroll 1
    for (int ch = 0; ch < 8; ch++) {
        const float* Rc = Rg + (size_t)ch * HWX;
        #pragma unroll 1
        for (int idx = tid; idx < HALO * HALO; idx += 256) {
            int rr = (idx * 1725) >> 16;         // idx / 38
            int cc = idx - rr * 38;
            int gr = gy0 + rr - 3, gc = gx0 + cc - 3;
            bool ok = ((unsigned)gr < (unsigned)HH) & ((unsigned)gc < (unsigned)WW);
            cpa4(dst + ch * SRCH + rr * SRP + cc,
                 ok ? (Rc + (size_t)gr * WW + gc) : safe, ok ? 4 : 0);
        }
    }
    asm volatile("cp.async.commit_group;" ::: "memory");
}

__global__ __launch_bounds__(256, 1) void k3_crf(const float* __restrict__ inF,
                                                 const float* __restrict__ logit,
                                                 float* __restrict__ out) {
    extern __shared__ char smem[];
    __nv_bfloat16* sF = (__nv_bfloat16*)smem;               // [49][1024] bf16
    float*         sR = (float*)(smem + 49 * 1024 * 2);     // [2][8][HALO*SRP]

    int b   = blockIdx.z;
    int gx0 = blockIdx.x * 32;
    int gy0 = blockIdx.y * 32;
    int tid = threadIdx.x;
    int tx  = tid & 7;          // 8 thread-cols * 4 px = 32 wide
    int ty  = tid >> 3;         // 32 rows
    int ox  = gx0 + 4 * tx;
    int oy  = gy0 + ty;

    const float* Rb = g_R + (size_t)b * CP * HWX;

    // F -> smem as bf16 (each thread: 49 float4 loads, coalesced)
    const float* Fb = inF + (size_t)b * 49 * HWX + (size_t)gy0 * WW + gx0;
    #pragma unroll 1
    for (int i = tid; i < 49 * 256; i += 256) {
        int p = i >> 8;
        int e = (i & 255) << 2;
        int row = e >> 5, col = e & 31;
        float4 v = *(const float4*)(Fb + (size_t)p * HWX + row * WW + col);
        __nv_bfloat162 lo = __floats2bfloat162_rn(v.x, v.y);
        __nv_bfloat162 hi = __floats2bfloat162_rn(v.z, v.w);
        *(uint2*)(sF + p * 1024 + e) = make_uint2(*reinterpret_cast<uint32_t*>(&lo),
                                                  *reinterpret_cast<uint32_t*>(&hi));
    }

    // prefetch group 0
    prefetch_group(sR, Rb, gx0, gy0, tid, Rb);

    #pragma unroll 1
    for (int g = 0; g < NGRP; g++) {
        asm volatile("cp.async.wait_group 0;" ::: "memory");
        __syncthreads();
        if (g + 1 < NGRP) {
            prefetch_group(sR + ((g + 1) & 1) * SRBUF,
                           Rb + (size_t)(8 * (g + 1)) * HWX, gx0, gy0, tid, Rb);
        }

        const float* bufp = sR + (g & 1) * SRBUF;

        float2 a01[8], a23[8];    // px pair {0,1} and {2,3} per channel
        #pragma unroll
        for (int ch = 0; ch < 8; ch++) {
            a01[ch] = make_float2(0.f, 0.f);
            a23[ch] = make_float2(0.f, 0.f);
        }

        #pragma unroll
        for (int di = 0; di < 7; di++) {
            // F taps for this di-row: (f0,f1) and (f2,f3) packed for 4 output px
            float2 fa[7], fb[7];
            #pragma unroll
            for (int dj = 0; dj < 7; dj++) {
                uint2 u = *(const uint2*)(sF + (di * 7 + dj) * 1024 + ty * 32 + 4 * tx);
                fa[dj] = make_float2(__uint_as_float(u.x << 16),
                                     __uint_as_float(u.x & 0xFFFF0000u));
                fb[dj] = make_float2(__uint_as_float(u.y << 16),
                                     __uint_as_float(u.y & 0xFFFF0000u));
            }
            int rbase = (ty + di) * SRP + 4 * tx;   // even -> 8B aligned
            #pragma unroll
            for (int ch = 0; ch < 8; ch++) {
                const float* rp = bufp + ch * SRCH + rbase;
                float2 P0 = *(const float2*)(rp + 0);
                float2 P1 = *(const float2*)(rp + 2);
                float2 P2 = *(const float2*)(rp + 4);
                float2 P3 = *(const float2*)(rp + 6);
                float2 P4 = *(const float2*)(rp + 8);
                float2 O0 = make_float2(P0.y, P1.x);
                float2 O1 = make_float2(P1.y, P2.x);
                float2 O2 = make_float2(P2.y, P3.x);
                float2 O3 = make_float2(P3.y, P4.x);
                // acc01 uses window pair at dj; acc23 at dj+2
                FMA2(a01[ch], fa[0], P0);  FMA2(a23[ch], fb[0], P1);
                FMA2(a01[ch], fa[1], O0);  FMA2(a23[ch], fb[1], O1);
                FMA2(a01[ch], fa[2], P1);  FMA2(a23[ch], fb[2], P2);
                FMA2(a01[ch], fa[3], O1);  FMA2(a23[ch], fb[3], O2);
                FMA2(a01[ch], fa[4], P2);  FMA2(a23[ch], fb[4], P3);
                FMA2(a01[ch], fa[5], O2);  FMA2(a23[ch], fb[5], O3);
                FMA2(a01[ch], fa[6], P3);  FMA2(a23[ch], fb[6], P4);
            }
        }

        int c0 = 8 * g;
        #pragma unroll
        for (int ch = 0; ch < 8; ch++) {
            int c = c0 + ch;
            if (c >= CC) break;
            size_t o = ((size_t)b * CC + c) * HWX + (size_t)oy * WW + ox;
            float4 lg = *(const float4*)(logit + o);
            float4 r;
            r.x = lg.x - a01[ch].x;
            r.y = lg.y - a01[ch].y;
            r.z = lg.z - a23[ch].x;
            r.w = lg.w - a23[ch].y;
            *(float4*)(out + o) = r;
        }
    }
}

// ---------------- launch --------------------------------------------------------------
extern "C" void kernel_launch(void* const* d_in, const int* in_sizes, int n_in,
                              void* d_out, int out_size) {
    const float* F      = (const float*)d_in[0];   // [B, 49, H, W]
    const float* logit  = (const float*)d_in[1];   // [B, C, H, W]
    const float* compat = (const float*)d_in[2];   // [C, C, 1, 1]
    float* out = (float*)d_out;

    cudaFuncSetAttribute(k2_gemm, cudaFuncAttributeMaxDynamicSharedMemorySize, SMEM_K2);
    cudaFuncSetAttribute(k3_crf,  cudaFuncAttributeMaxDynamicSharedMemorySize, K3_SMEM);

    k0_comp<<<(CP * CP + 255) / 256, 256>>>(compat);
    k2_gemm<<<dim3(HWX / 128, BB), 256, SMEM_K2>>>(logit);
    k3_crf<<<dim3(WW / 32, HH / 32, BB), 256, K3_SMEM>>>(F, logit, out);
}

// round 12
// speedup vs baseline: 1.2142x; 1.0522x over previous
#include <cuda_runtime.h>
#include <cuda_bf16.h>
#include <cstdint>

// Problem constants
#define BB   4
#define CC   150
#define CP   160          // padded channels; row CC holds the ones-row (sum)
#define HH   320
#define WW   320
#define HWX  (HH*WW)      // 102400
#define KP   168          // k2 smem K stride (bf16 elems), conflict-free

// ---------------- scratch (static device memory) -------------------------------------
__device__ __nv_bfloat16 g_comp[CP * CP];              // sigmoid(100*compat), bf16; row 150 = ones
__device__ float         g_R[(size_t)BB * CP * HWX];   // normalized R; rows 150..151 zeroed by k2

// ---------------- K0: compatibility -> sigmoid -> bf16 (+ ones row) -------------------
__global__ void k0_comp(const float* __restrict__ compat) {
    int t = blockIdx.x * blockDim.x + threadIdx.x;
    if (t >= CP * CP) return;
    int o = t / CP, i = t - o * CP;
    float v = 0.f;
    if (i < CC) {
        if (o < CC) {
            float x = 100.0f * compat[o * CC + i];
            v = 1.0f / (1.0f + __expf(-x));
        } else if (o == CC) {
            v = 1.0f;                    // sum row
        }
    }
    g_comp[t] = __float2bfloat16(v);
}

// ---------------- K2: fused softmax + GEMM (legacy mma.sync path) ---------------------
// R[b,o,n] = (sum_k comp[o,k] * exp(logit[b,k,n])) / (sum_k exp(logit[b,k,n]))
__device__ __forceinline__ void mma16816(float* c,
                                         uint32_t a0, uint32_t a1, uint32_t a2, uint32_t a3,
                                         uint32_t b0, uint32_t b1) {
    asm volatile(
        "mma.sync.aligned.m16n8k16.row.col.f32.bf16.bf16.f32 "
        "{%0,%1,%2,%3}, {%4,%5,%6,%7}, {%8,%9}, {%0,%1,%2,%3};\n"
        : "+f"(c[0]), "+f"(c[1]), "+f"(c[2]), "+f"(c[3])
        : "r"(a0), "r"(a1), "r"(a2), "r"(a3), "r"(b0), "r"(b1));
}

#define SMEM_K2 ((CP * KP + 128 * KP) * 2)   // 96768 bytes

__global__ __launch_bounds__(256) void k2_gemm(const float* __restrict__ logit) {
    extern __shared__ __nv_bfloat16 sm[];
    __nv_bfloat16* sA = sm;                 // [CP][KP]  comp, row-major (m,k)
    __nv_bfloat16* sB = sm + CP * KP;       // [128][KP] exp(logit) transposed: (n, k)

    int b  = blockIdx.y;
    int n0 = blockIdx.x * 128;
    int tid = threadIdx.x;

    // load A (comp)
    for (int idx = tid; idx < CP * CP; idx += 256) {
        int m = idx / CP, k = idx - m * CP;
        sA[m * KP + k] = g_comp[idx];
    }
    // B fill with fused exp: each thread produces 8 consecutive k for one nn -> STS.128
    const float* Lb = logit + (size_t)b * CC * HWX + n0;
    for (int t = tid; t < 20 * 128; t += 256) {
        int ko = t >> 7, nn = t & 127;
        int kb = ko * 8;
        float e[8];
        #pragma unroll
        for (int j = 0; j < 8; j++) {
            int kk = kb + j;
            e[j] = (kk < CC) ? __expf(Lb[(size_t)kk * HWX + nn]) : 0.f;
        }
        __nv_bfloat162 p0 = __floats2bfloat162_rn(e[0], e[1]);
        __nv_bfloat162 p1 = __floats2bfloat162_rn(e[2], e[3]);
        __nv_bfloat162 p2 = __floats2bfloat162_rn(e[4], e[5]);
        __nv_bfloat162 p3 = __floats2bfloat162_rn(e[6], e[7]);
        uint4 pk;
        pk.x = *reinterpret_cast<uint32_t*>(&p0);
        pk.y = *reinterpret_cast<uint32_t*>(&p1);
        pk.z = *reinterpret_cast<uint32_t*>(&p2);
        pk.w = *reinterpret_cast<uint32_t*>(&p3);
        *(uint4*)&sB[nn * KP + kb] = pk;
    }
    __syncthreads();

    int warp = tid >> 5, lane = tid & 31;
    int gid = lane >> 2, tig = lane & 3;
    int nt0 = warp * 2;

    float acc[10][2][4];
    #pragma unroll
    for (int mt = 0; mt < 10; mt++)
        #pragma unroll
        for (int nt = 0; nt < 2; nt++)
            #pragma unroll
            for (int q = 0; q < 4; q++) acc[mt][nt][q] = 0.f;

    #pragma unroll
    for (int k0 = 0; k0 < CP; k0 += 16) {
        uint32_t bf[2][2];
        #pragma unroll
        for (int nt = 0; nt < 2; nt++) {
            int n = (nt0 + nt) * 8 + gid;
            const uint32_t* p = (const uint32_t*)&sB[n * KP + k0];
            bf[nt][0] = p[tig];
            bf[nt][1] = p[tig + 4];
        }
        #pragma unroll
        for (int mt = 0; mt < 10; mt++) {
            int m = mt * 16 + gid;
            const uint32_t* pa0 = (const uint32_t*)&sA[m * KP + k0];
            const uint32_t* pa1 = (const uint32_t*)&sA[(m + 8) * KP + k0];
            uint32_t a0 = pa0[tig], a1 = pa1[tig], a2 = pa0[tig + 4], a3 = pa1[tig + 4];
            #pragma unroll
            for (int nt = 0; nt < 2; nt++)
                mma16816(acc[mt][nt], a0, a1, a2, a3, bf[nt][0], bf[nt][1]);
        }
    }

    // epilogue: recover per-column sums from row 150 via shfl, normalize, store
    float* Rb = g_R + (size_t)b * CP * HWX + n0;
    #pragma unroll
    for (int nt = 0; nt < 2; nt++) {
        // lane 24+tig (gid=6) holds row 150 for columns 2tig, 2tig+1 in acc[9][nt][0..1]
        float s0 = __shfl_sync(0xffffffffu, acc[9][nt][0], 24 + tig);
        float s1 = __shfl_sync(0xffffffffu, acc[9][nt][1], 24 + tig);
        float i0 = 1.0f / s0, i1 = 1.0f / s1;
        int col = (nt0 + nt) * 8 + 2 * tig;
        #pragma unroll
        for (int mt = 0; mt < 10; mt++) {
            int row = mt * 16 + gid;
            float v0 = (row < CC) ? acc[mt][nt][0] * i0 : 0.f;   // rows 150..151 -> 0
            float v1 = (row < CC) ? acc[mt][nt][1] * i1 : 0.f;
            *(float2*)&Rb[(size_t)row * HWX + col] = make_float2(v0, v1);
            if (mt < 9) {   // rows 152..159 never read -> skip
                *(float2*)&Rb[(size_t)(row + 8) * HWX + col] =
                    make_float2(acc[mt][nt][2] * i0, acc[mt][nt][3] * i1);
            }
        }
    }
}

// ---------------- K3: out = logit - CRF(F, R) ---------------------------------------
// 128 thr, 32x16 tile (thread = 4px x 8ch), 2 blocks/SM.
// F staged in smem as bf16 (read from DRAM once). R halo double-buffered via cp.async.
// SRP=44 -> 16B-aligned windows, conflict-free LDS.128 loads. Inner product fma.rn.f32x2.
#define TH    16                   // tile height
#define HALO_R (TH + 6)            // 22
#define HALO_C 38
#define SRP   44                   // floats per halo row (16B-aligned windows)
#define SRCH  (HALO_R * SRP)       // 968 floats per channel
#define SRBUF (8 * SRCH)           // 7744 floats per buffer
#define NGRP  19                   // 19 x 8 = 152 >= 150 (rows 150,151 are zero)
#define FSM   (49 * 512)           // F tile elems (bf16)
#define K3_SMEM (FSM * 2 + 2 * SRBUF * 4)   // 50176 + 61952 = 112128 B

__device__ __forceinline__ void FMA2(float2& d, const float2& a, const float2& b) {
    asm("fma.rn.f32x2 %0, %1, %2, %0;"
        : "+l"(reinterpret_cast<unsigned long long&>(d))
        : "l"(reinterpret_cast<const unsigned long long&>(a)),
          "l"(reinterpret_cast<const unsigned long long&>(b)));
}
__device__ __forceinline__ void cpa4(float* dst, const float* src, int sz) {
    unsigned d = (unsigned)__cvta_generic_to_shared(dst);
    asm volatile("cp.async.ca.shared.global [%0], [%1], 4, %2;"
                 :: "r"(d), "l"(src), "r"(sz) : "memory");
}
__device__ __forceinline__ void prefetch_group(float* dst, const float* Rg,
                                               int gx0, int gy0, int tid,
                                               const float* safe) {
    #pragma unroll 1
    for (int ch = 0; ch < 8; ch++) {
        const float* Rc = Rg + (size_t)ch * HWX;
        #pragma unroll 1
        for (int idx = tid; idx < HALO_R * HALO_C; idx += 128) {
            int rr = (idx * 1725) >> 16;         // idx / 38 (valid for idx < 1444)
            int cc = idx - rr * 38;
            int gr = gy0 + rr - 3, gc = gx0 + cc - 3;
            bool ok = ((unsigned)gr < (unsigned)HH) & ((unsigned)gc < (unsigned)WW);
            cpa4(dst + ch * SRCH + rr * SRP + cc,
                 ok ? (Rc + (size_t)gr * WW + gc) : safe, ok ? 4 : 0);
        }
    }
    asm volatile("cp.async.commit_group;" ::: "memory");
}

__global__ __launch_bounds__(128, 2) void k3_crf(const float* __restrict__ inF,
                                                 const float* __restrict__ logit,
                                                 float* __restrict__ out) {
    extern __shared__ char smem[];
    __nv_bfloat16* sF = (__nv_bfloat16*)smem;                // [49][512] bf16
    float*         sR = (float*)(smem + FSM * 2);            // [2][8][SRCH]

    int b   = blockIdx.z;
    int gx0 = blockIdx.x * 32;
    int gy0 = blockIdx.y * TH;
    int tid = threadIdx.x;
    int tx  = tid & 7;          // 8 thread-cols * 4 px = 32 wide
    int ty  = tid >> 3;         // 16 rows
    int ox  = gx0 + 4 * tx;
    int oy  = gy0 + ty;

    const float* Rb = g_R + (size_t)b * CP * HWX;

    // F -> smem as bf16 (each thread: 49 float4 loads, coalesced)
    const float* Fb = inF + (size_t)b * 49 * HWX + (size_t)gy0 * WW + gx0;
    #pragma unroll 1
    for (int i = tid; i < 49 * 128; i += 128) {
        int p = i >> 7;
        int e = (i & 127) << 2;          // 0..508
        int row = e >> 5, col = e & 31;
        float4 v = *(const float4*)(Fb + (size_t)p * HWX + row * WW + col);
        __nv_bfloat162 lo = __floats2bfloat162_rn(v.x, v.y);
        __nv_bfloat162 hi = __floats2bfloat162_rn(v.z, v.w);
        *(uint2*)(sF + p * 512 + e) = make_uint2(*reinterpret_cast<uint32_t*>(&lo),
                                                 *reinterpret_cast<uint32_t*>(&hi));
    }

    prefetch_group(sR, Rb, gx0, gy0, tid, Rb);

    #pragma unroll 1
    for (int g = 0; g < NGRP; g++) {
        asm volatile("cp.async.wait_group 0;" ::: "memory");
        __syncthreads();
        if (g + 1 < NGRP) {
            prefetch_group(sR + ((g + 1) & 1) * SRBUF,
                           Rb + (size_t)(8 * (g + 1)) * HWX, gx0, gy0, tid, Rb);
        }

        const float* bufp = sR + (g & 1) * SRBUF;

        float2 a01[8], a23[8];    // px pair {0,1} and {2,3} per channel
        #pragma unroll
        for (int ch = 0; ch < 8; ch++) {
            a01[ch] = make_float2(0.f, 0.f);
            a23[ch] = make_float2(0.f, 0.f);
        }

        #pragma unroll
        for (int di = 0; di < 7; di++) {
            // F taps for this di-row: (f0,f1) and (f2,f3) packed for 4 output px
            float2 fa[7], fb[7];
            #pragma unroll
            for (int dj = 0; dj < 7; dj++) {
                uint2 u = *(const uint2*)(sF + (di * 7 + dj) * 512 + ty * 32 + 4 * tx);
                fa[dj] = make_float2(__uint_as_float(u.x << 16),
                                     __uint_as_float(u.x & 0xFFFF0000u));
                fb[dj] = make_float2(__uint_as_float(u.y << 16),
                                     __uint_as_float(u.y & 0xFFFF0000u));
            }
            int rbase = (ty + di) * SRP + 4 * tx;   // multiple of 4 floats -> 16B aligned
            #pragma unroll
            for (int ch = 0; ch < 8; ch++) {
                const float* rp = bufp + ch * SRCH + rbase;
                float4 A = *(const float4*)(rp + 0);   // w0..w3
                float4 Bq = *(const float4*)(rp + 4);  // w4..w7
                float2 T = *(const float2*)(rp + 8);   // w8..w9
                float2 P0 = make_float2(A.x, A.y);
                float2 P1 = make_float2(A.z, A.w);
                float2 P2 = make_float2(Bq.x, Bq.y);
                float2 P3 = make_float2(Bq.z, Bq.w);
                float2 P4 = T;
                float2 O0 = make_float2(A.y, A.z);
                float2 O1 = make_float2(A.w, Bq.x);
                float2 O2 = make_float2(Bq.y, Bq.z);
                float2 O3 = make_float2(Bq.w, T.x);
                FMA2(a01[ch], fa[0], P0);  FMA2(a23[ch], fb[0], P1);
                FMA2(a01[ch], fa[1], O0);  FMA2(a23[ch], fb[1], O1);
                FMA2(a01[ch], fa[2], P1);  FMA2(a23[ch], fb[2], P2);
                FMA2(a01[ch], fa[3], O1);  FMA2(a23[ch], fb[3], O2);
                FMA2(a01[ch], fa[4], P2);  FMA2(a23[ch], fb[4], P3);
                FMA2(a01[ch], fa[5], O2);  FMA2(a23[ch], fb[5], O3);
                FMA2(a01[ch], fa[6], P3);  FMA2(a23[ch], fb[6], P4);
            }
        }

        int c0 = 8 * g;
        #pragma unroll
        for (int ch = 0; ch < 8; ch++) {
            int c = c0 + ch;
            if (c >= CC) break;
            size_t o = ((size_t)b * CC + c) * HWX + (size_t)oy * WW + ox;
            float4 lg = *(const float4*)(logit + o);
            float4 r;
            r.x = lg.x - a01[ch].x;
            r.y = lg.y - a01[ch].y;
            r.z = lg.z - a23[ch].x;
            r.w = lg.w - a23[ch].y;
            *(float4*)(out + o) = r;
        }
    }
}

// ---------------- launch --------------------------------------------------------------
extern "C" void kernel_launch(void* const* d_in, const int* in_sizes, int n_in,
                              void* d_out, int out_size) {
    const float* F      = (const float*)d_in[0];   // [B, 49, H, W]
    const float* logit  = (const float*)d_in[1];   // [B, C, H, W]
    const float* compat = (const float*)d_in[2];   // [C, C, 1, 1]
    float* out = (float*)d_out;

    cudaFuncSetAttribute(k2_gemm, cudaFuncAttributeMaxDynamicSharedMemorySize, SMEM_K2);
    cudaFuncSetAttribute(k3_crf,  cudaFuncAttributeMaxDynamicSharedMemorySize, K3_SMEM);

    k0_comp<<<(CP * CP + 255) / 256, 256>>>(compat);
    k2_gemm<<<dim3(HWX / 128, BB), 256, SMEM_K2>>>(logit);
    k3_crf<<<dim3(WW / 32, HH / TH, BB), 128, K3_SMEM>>>(F, logit, out);
}

// round 14
// speedup vs baseline: 1.3176x; 1.0851x over previous
#include <cuda_runtime.h>
#include <cuda_bf16.h>
#include <cstdint>

// Problem constants
#define BB   4
#define CC   150
#define CP   160          // padded channels; row CC holds the ones-row (sum)
#define HH   320
#define WW   320
#define HWX  (HH*WW)      // 102400
#define KP   168          // k2 smem K stride (bf16 elems), conflict-free

// ---------------- scratch (static device memory) -------------------------------------
__device__ __nv_bfloat16 g_comp[CP * CP];              // sigmoid(100*compat), bf16; row 150 = ones
__device__ float         g_R[(size_t)BB * CP * HWX];   // normalized R; rows 150..151 zeroed by k2

// ---------------- K0: compatibility -> sigmoid -> bf16 (+ ones row) -------------------
__global__ void k0_comp(const float* __restrict__ compat) {
    int t = blockIdx.x * blockDim.x + threadIdx.x;
    if (t >= CP * CP) return;
    int o = t / CP, i = t - o * CP;
    float v = 0.f;
    if (i < CC) {
        if (o < CC) {
            float x = 100.0f * compat[o * CC + i];
            v = 1.0f / (1.0f + __expf(-x));
        } else if (o == CC) {
            v = 1.0f;                    // sum row
        }
    }
    g_comp[t] = __float2bfloat16(v);
}

// ---------------- K2: fused softmax + GEMM (legacy mma.sync path) ---------------------
// R[b,o,n] = (sum_k comp[o,k] * exp(logit[b,k,n])) / (sum_k exp(logit[b,k,n]))
__device__ __forceinline__ void mma16816(float* c,
                                         uint32_t a0, uint32_t a1, uint32_t a2, uint32_t a3,
                                         uint32_t b0, uint32_t b1) {
    asm volatile(
        "mma.sync.aligned.m16n8k16.row.col.f32.bf16.bf16.f32 "
        "{%0,%1,%2,%3}, {%4,%5,%6,%7}, {%8,%9}, {%0,%1,%2,%3};\n"
        : "+f"(c[0]), "+f"(c[1]), "+f"(c[2]), "+f"(c[3])
        : "r"(a0), "r"(a1), "r"(a2), "r"(a3), "r"(b0), "r"(b1));
}

#define SMEM_K2 ((CP * KP + 128 * KP) * 2)   // 96768 bytes

__global__ __launch_bounds__(256, 2) void k2_gemm(const float* __restrict__ logit) {
    extern __shared__ __nv_bfloat16 sm[];
    __nv_bfloat16* sA = sm;                 // [CP][KP]  comp, row-major (m,k)
    __nv_bfloat16* sB = sm + CP * KP;       // [128][KP] exp(logit) transposed: (n, k)

    int b  = blockIdx.y;
    int n0 = blockIdx.x * 128;
    int tid = threadIdx.x;

    // load A (comp)
    for (int idx = tid; idx < CP * CP; idx += 256) {
        int m = idx / CP, k = idx - m * CP;
        sA[m * KP + k] = g_comp[idx];
    }
    // B fill with fused exp: each thread produces 8 consecutive k for one nn -> STS.128
    const float* Lb = logit + (size_t)b * CC * HWX + n0;
    for (int t = tid; t < 20 * 128; t += 256) {
        int ko = t >> 7, nn = t & 127;
        int kb = ko * 8;
        float e[8];
        #pragma unroll
        for (int j = 0; j < 8; j++) {
            int kk = kb + j;
            e[j] = (kk < CC) ? __expf(Lb[(size_t)kk * HWX + nn]) : 0.f;
        }
        __nv_bfloat162 p0 = __floats2bfloat162_rn(e[0], e[1]);
        __nv_bfloat162 p1 = __floats2bfloat162_rn(e[2], e[3]);
        __nv_bfloat162 p2 = __floats2bfloat162_rn(e[4], e[5]);
        __nv_bfloat162 p3 = __floats2bfloat162_rn(e[6], e[7]);
        uint4 pk;
        pk.x = *reinterpret_cast<uint32_t*>(&p0);
        pk.y = *reinterpret_cast<uint32_t*>(&p1);
        pk.z = *reinterpret_cast<uint32_t*>(&p2);
        pk.w = *reinterpret_cast<uint32_t*>(&p3);
        *(uint4*)&sB[nn * KP + kb] = pk;
    }
    __syncthreads();

    int warp = tid >> 5, lane = tid & 31;
    int gid = lane >> 2, tig = lane & 3;
    int nt0 = warp * 2;

    float acc[10][2][4];
    #pragma unroll
    for (int mt = 0; mt < 10; mt++)
        #pragma unroll
        for (int nt = 0; nt < 2; nt++)
            #pragma unroll
            for (int q = 0; q < 4; q++) acc[mt][nt][q] = 0.f;

    #pragma unroll
    for (int k0 = 0; k0 < CP; k0 += 16) {
        uint32_t bf[2][2];
        #pragma unroll
        for (int nt = 0; nt < 2; nt++) {
            int n = (nt0 + nt) * 8 + gid;
            const uint32_t* p = (const uint32_t*)&sB[n * KP + k0];
            bf[nt][0] = p[tig];
            bf[nt][1] = p[tig + 4];
        }
        #pragma unroll
        for (int mt = 0; mt < 10; mt++) {
            int m = mt * 16 + gid;
            const uint32_t* pa0 = (const uint32_t*)&sA[m * KP + k0];
            const uint32_t* pa1 = (const uint32_t*)&sA[(m + 8) * KP + k0];
            uint32_t a0 = pa0[tig], a1 = pa1[tig], a2 = pa0[tig + 4], a3 = pa1[tig + 4];
            #pragma unroll
            for (int nt = 0; nt < 2; nt++)
                mma16816(acc[mt][nt], a0, a1, a2, a3, bf[nt][0], bf[nt][1]);
        }
    }

    // epilogue: recover per-column sums from row 150 via shfl, normalize, store
    float* Rb = g_R + (size_t)b * CP * HWX + n0;
    #pragma unroll
    for (int nt = 0; nt < 2; nt++) {
        // lane 24+tig (gid=6) holds row 150 for columns 2tig, 2tig+1 in acc[9][nt][0..1]
        float s0 = __shfl_sync(0xffffffffu, acc[9][nt][0], 24 + tig);
        float s1 = __shfl_sync(0xffffffffu, acc[9][nt][1], 24 + tig);
        float i0 = 1.0f / s0, i1 = 1.0f / s1;
        int col = (nt0 + nt) * 8 + 2 * tig;
        #pragma unroll
        for (int mt = 0; mt < 10; mt++) {
            int row = mt * 16 + gid;
            float v0 = (row < CC) ? acc[mt][nt][0] * i0 : 0.f;   // rows 150..151 -> 0
            float v1 = (row < CC) ? acc[mt][nt][1] * i1 : 0.f;
            *(float2*)&Rb[(size_t)row * HWX + col] = make_float2(v0, v1);
            if (mt < 9) {   // rows 152..159 never read -> skip
                *(float2*)&Rb[(size_t)(row + 8) * HWX + col] =
                    make_float2(acc[mt][nt][2] * i0, acc[mt][nt][3] * i1);
            }
        }
    }
}

// ---------------- K3: out = logit - CRF(F, R) ---------------------------------------
// 128 thr, 32x16 tile (thread = 4px x 8ch), 2 blocks/SM.
// Halo layout: 22 rows x 40 cols per channel, col 0 <-> global gx0-4 (16B aligned).
// Interior blocks fill halo with aligned cp.async.16 row segments (no predication);
// border blocks use predicated 4B cp.async with zfill. Windows: 3x LDS.128 (w1..w10).
#define TH     16                  // tile height
#define HALO_R 22                  // TH + 6
#define HALO_C 40
#define SRP    44                  // floats per halo row (16B-aligned)
#define SRCH   (HALO_R * SRP)      // 968 floats per channel
#define SRBUF  (8 * SRCH)          // 7744 floats per buffer
#define NGRP   19                  // 19 x 8 = 152 >= 150 (rows 150,151 are zero)
#define FSM    (49 * 512)          // F tile elems (bf16)
#define K3_SMEM (FSM * 2 + 2 * SRBUF * 4)   // 50176 + 61952 = 112128 B

__device__ __forceinline__ void FMA2(float2& d, const float2& a, const float2& b) {
    asm("fma.rn.f32x2 %0, %1, %2, %0;"
        : "+l"(reinterpret_cast<unsigned long long&>(d))
        : "l"(reinterpret_cast<const unsigned long long&>(a)),
          "l"(reinterpret_cast<const unsigned long long&>(b)));
}
__device__ __forceinline__ void cpa4(float* dst, const float* src, int sz) {
    unsigned d = (unsigned)__cvta_generic_to_shared(dst);
    asm volatile("cp.async.ca.shared.global [%0], [%1], 4, %2;"
                 :: "r"(d), "l"(src), "r"(sz) : "memory");
}
__device__ __forceinline__ void cpa16(float* dst, const float* src) {
    unsigned d = (unsigned)__cvta_generic_to_shared(dst);
    asm volatile("cp.async.cg.shared.global [%0], [%1], 16;"
                 :: "r"(d), "l"(src) : "memory");
}

// Border-safe fill: per-element predicated 4B cp.async (zfill OOB / padded channels)
__device__ __forceinline__ void prefetch_border(float* dst, const float* Rg,
                                                int gx0, int gy0, int tid,
                                                const float* safe) {
    #pragma unroll 1
    for (int ch = 0; ch < 8; ch++) {
        const float* Rc = Rg + (size_t)ch * HWX;
        #pragma unroll 1
        for (int idx = tid; idx < HALO_R * HALO_C; idx += 128) {
            int rr = (idx * 1639) >> 16;         // idx / 40 (valid for idx < 880)
            int cc = idx - rr * 40;
            int gr = gy0 + rr - 3, gc = gx0 + cc - 4;
            bool ok = ((unsigned)gr < (unsigned)HH) & ((unsigned)gc < (unsigned)WW);
            cpa4(dst + ch * SRCH + rr * SRP + cc,
                 ok ? (Rc + (size_t)gr * WW + gc) : safe, ok ? 4 : 0);
        }
    }
    asm volatile("cp.async.commit_group;" ::: "memory");
}

// Interior fill: rows fully in-bounds; 10 aligned 16B copies per row per channel
__device__ __forceinline__ void prefetch_interior(float* dst, const float* Rg,
                                                  int gx0, int gy0, int tid) {
    #pragma unroll 1
    for (int ch = 0; ch < 8; ch++) {
        const float* rowbase = Rg + (size_t)ch * HWX + (size_t)(gy0 - 3) * WW + (gx0 - 4);
        float* dch = dst + ch * SRCH;
        #pragma unroll 1
        for (int i = tid; i < HALO_R * 10; i += 128) {     // 220 segments
            int rr = (i * 6554) >> 16;                      // i / 10
            int q4 = (i - rr * 10) * 4;
            cpa16(dch + rr * SRP + q4, rowbase + rr * WW + q4);
        }
    }
    asm volatile("cp.async.commit_group;" ::: "memory");
}

__global__ __launch_bounds__(128, 2) void k3_crf(const float* __restrict__ inF,
                                                 const float* __restrict__ logit,
                                                 float* __restrict__ out) {
    extern __shared__ char smem[];
    __nv_bfloat16* sF = (__nv_bfloat16*)smem;                // [49][512] bf16
    float*         sR = (float*)(smem + FSM * 2);            // [2][8][SRCH]

    int b   = blockIdx.z;
    int gx0 = blockIdx.x * 32;
    int gy0 = blockIdx.y * TH;
    int tid = threadIdx.x;
    int tx  = tid & 7;          // 8 thread-cols * 4 px = 32 wide
    int ty  = tid >> 3;         // 16 rows
    int ox  = gx0 + 4 * tx;
    int oy  = gy0 + ty;

    // interior <=> whole 22x40 halo in-bounds
    bool interior = (gy0 >= 3) && (gy0 + TH + 2 < HH) && (gx0 >= 4) && (gx0 + 35 < WW);

    const float* Rb = g_R + (size_t)b * CP * HWX;

    // F -> smem as bf16 (each thread: 49 float4 loads, coalesced)
    const float* Fb = inF + (size_t)b * 49 * HWX + (size_t)gy0 * WW + gx0;
    #pragma unroll 1
    for (int i = tid; i < 49 * 128; i += 128) {
        int p = i >> 7;
        int e = (i & 127) << 2;          // 0..508
        int row = e >> 5, col = e & 31;
        float4 v = *(const float4*)(Fb + (size_t)p * HWX + row * WW + col);
        __nv_bfloat162 lo = __floats2bfloat162_rn(v.x, v.y);
        __nv_bfloat162 hi = __floats2bfloat162_rn(v.z, v.w);
        *(uint2*)(sF + p * 512 + e) = make_uint2(*reinterpret_cast<uint32_t*>(&lo),
                                                 *reinterpret_cast<uint32_t*>(&hi));
    }

    if (interior) prefetch_interior(sR, Rb, gx0, gy0, tid);
    else          prefetch_border(sR, Rb, gx0, gy0, tid, Rb);

    #pragma unroll 1
    for (int g = 0; g < NGRP; g++) {
        asm volatile("cp.async.wait_group 0;" ::: "memory");
        __syncthreads();
        if (g + 1 < NGRP) {
            float* nb = sR + ((g + 1) & 1) * SRBUF;
            const float* Rg = Rb + (size_t)(8 * (g + 1)) * HWX;
            if (interior) prefetch_interior(nb, Rg, gx0, gy0, tid);
            else          prefetch_border(nb, Rg, gx0, gy0, tid, Rb);
        }

        const float* bufp = sR + (g & 1) * SRBUF;

        float2 a01[8], a23[8];    // px pair {0,1} and {2,3} per channel
        #pragma unroll
        for (int ch = 0; ch < 8; ch++) {
            a01[ch] = make_float2(0.f, 0.f);
            a23[ch] = make_float2(0.f, 0.f);
        }

        #pragma unroll
        for (int di = 0; di < 7; di++) {
            // F taps for this di-row: (f0,f1) and (f2,f3) packed for 4 output px
            float2 fa[7], fb[7];
            #pragma unroll
            for (int dj = 0; dj < 7; dj++) {
                uint2 u = *(const uint2*)(sF + (di * 7 + dj) * 512 + ty * 32 + 4 * tx);
                fa[dj] = make_float2(__uint_as_float(u.x << 16),
                                     __uint_as_float(u.x & 0xFFFF0000u));
                fb[dj] = make_float2(__uint_as_float(u.y << 16),
                                     __uint_as_float(u.y & 0xFFFF0000u));
            }
            int rbase = (ty + di) * SRP + 4 * tx;   // 16B aligned
            #pragma unroll
            for (int ch = 0; ch < 8; ch++) {
                const float* rp = bufp + ch * SRCH + rbase;
                float4 A  = *(const float4*)(rp + 0);   // w0..w3
                float4 Bq = *(const float4*)(rp + 4);   // w4..w7
                float4 Cq = *(const float4*)(rp + 8);   // w8..w11
                // output px p, tap dj -> window w[p+dj+1]
                float2 P0 = make_float2(A.y,  A.z);     // (w1,w2)
                float2 P1 = make_float2(A.w,  Bq.x);    // (w3,w4)
                float2 P2 = make_float2(Bq.y, Bq.z);    // (w5,w6)
                float2 P3 = make_float2(Bq.w, Cq.x);    // (w7,w8)
                float2 P4 = make_float2(Cq.y, Cq.z);    // (w9,w10)
                float2 O0 = make_float2(A.z,  A.w);     // (w2,w3)
                float2 O1 = make_float2(Bq.x, Bq.y);    // (w4,w5)
                float2 O2 = make_float2(Bq.z, Bq.w);    // (w6,w7)
                float2 O3 = make_float2(Cq.x, Cq.y);    // (w8,w9)
                FMA2(a01[ch], fa[0], P0);  FMA2(a23[ch], fb[0], P1);
                FMA2(a01[ch], fa[1], O0);  FMA2(a23[ch], fb[1], O1);
                FMA2(a01[ch], fa[2], P1);  FMA2(a23[ch], fb[2], P2);
                FMA2(a01[ch], fa[3], O1);  FMA2(a23[ch], fb[3], O2);
                FMA2(a01[ch], fa[4], P2);  FMA2(a23[ch], fb[4], P3);
                FMA2(a01[ch], fa[5], O2);  FMA2(a23[ch], fb[5], O3);
                FMA2(a01[ch], fa[6], P3);  FMA2(a23[ch], fb[6], P4);
            }
        }

        int c0 = 8 * g;
        #pragma unroll
        for (int ch = 0; ch < 8; ch++) {
            int c = c0 + ch;
            if (c >= CC) break;
            size_t o = ((size_t)b * CC + c) * HWX + (size_t)oy * WW + ox;
            float4 lg = *(const float4*)(logit + o);
            float4 r;
            r.x = lg.x - a01[ch].x;
            r.y = lg.y - a01[ch].y;
            r.z = lg.z - a23[ch].x;
            r.w = lg.w - a23[ch].y;
            *(float4*)(out + o) = r;
        }
    }
}

// ---------------- launch --------------------------------------------------------------
extern "C" void kernel_launch(void* const* d_in, const int* in_sizes, int n_in,
                              void* d_out, int out_size) {
    const float* F      = (const float*)d_in[0];   // [B, 49, H, W]
    const float* logit  = (const float*)d_in[1];   // [B, C, H, W]
    const float* compat = (const float*)d_in[2];   // [C, C, 1, 1]
    float* out = (float*)d_out;

    cudaFuncSetAttribute(k2_gemm, cudaFuncAttributeMaxDynamicSharedMemorySize, SMEM_K2);
    cudaFuncSetAttribute(k3_crf,  cudaFuncAttributeMaxDynamicSharedMemorySize, K3_SMEM);

    k0_comp<<<(CP * CP + 255) / 256, 256>>>(compat);
    k2_gemm<<<dim3(HWX / 128, BB), 256, SMEM_K2>>>(logit);
    k3_crf<<<dim3(WW / 32, HH / TH, BB), 128, K3_SMEM>>>(F, logit, out);
}

// round 16
// speedup vs baseline: 1.3228x; 1.0039x over previous
#include <cuda_runtime.h>
#include <cuda_bf16.h>
#include <cstdint>

// Problem constants
#define BB   4
#define CC   150
#define CP   160          // padded channels; row CC holds the ones-row (sum)
#define HH   320
#define WW   320
#define HWX  (HH*WW)      // 102400
#define KP   168          // k2 smem K stride (bf16 elems), conflict-free

// ---------------- scratch (static device memory) -------------------------------------
__device__ __nv_bfloat16 g_comp[CP * CP];               // sigmoid(100*compat); row 150 = ones
__device__ __nv_bfloat16 g_Rh[(size_t)BB * CP * HWX];   // normalized R (bf16); rows 150/151
                                                        // zeroed by k2, 152..159 stay 0-init

// ---------------- K0: compatibility -> sigmoid -> bf16 (+ ones row) -------------------
__global__ void k0_comp(const float* __restrict__ compat) {
    int t = blockIdx.x * blockDim.x + threadIdx.x;
    if (t >= CP * CP) return;
    int o = t / CP, i = t - o * CP;
    float v = 0.f;
    if (i < CC) {
        if (o < CC) {
            float x = 100.0f * compat[o * CC + i];
            v = 1.0f / (1.0f + __expf(-x));
        } else if (o == CC) {
            v = 1.0f;                    // sum row
        }
    }
    g_comp[t] = __float2bfloat16(v);
}

// ---------------- K2: fused softmax + GEMM (legacy mma.sync path) ---------------------
// R[b,o,n] = (sum_k comp[o,k] * exp(logit[b,k,n])) / (sum_k exp(logit[b,k,n]))
__device__ __forceinline__ void mma16816(float* c,
                                         uint32_t a0, uint32_t a1, uint32_t a2, uint32_t a3,
                                         uint32_t b0, uint32_t b1) {
    asm volatile(
        "mma.sync.aligned.m16n8k16.row.col.f32.bf16.bf16.f32 "
        "{%0,%1,%2,%3}, {%4,%5,%6,%7}, {%8,%9}, {%0,%1,%2,%3};\n"
        : "+f"(c[0]), "+f"(c[1]), "+f"(c[2]), "+f"(c[3])
        : "r"(a0), "r"(a1), "r"(a2), "r"(a3), "r"(b0), "r"(b1));
}

#define SMEM_K2 ((CP * KP + 128 * KP) * 2)   // 96768 bytes

__global__ __launch_bounds__(256, 2) void k2_gemm(const float* __restrict__ logit) {
    extern __shared__ __nv_bfloat16 sm[];
    __nv_bfloat16* sA = sm;                 // [CP][KP]  comp, row-major (m,k)
    __nv_bfloat16* sB = sm + CP * KP;       // [128][KP] exp(logit) transposed: (n, k)

    int b  = blockIdx.y;
    int n0 = blockIdx.x * 128;
    int tid = threadIdx.x;

    // load A (comp)
    for (int idx = tid; idx < CP * CP; idx += 256) {
        int m = idx / CP, k = idx - m * CP;
        sA[m * KP + k] = g_comp[idx];
    }
    // B fill with fused exp: each thread produces 8 consecutive k for one nn -> STS.128
    const float* Lb = logit + (size_t)b * CC * HWX + n0;
    for (int t = tid; t < 20 * 128; t += 256) {
        int ko = t >> 7, nn = t & 127;
        int kb = ko * 8;
        float e[8];
        #pragma unroll
        for (int j = 0; j < 8; j++) {
            int kk = kb + j;
            e[j] = (kk < CC) ? __expf(Lb[(size_t)kk * HWX + nn]) : 0.f;
        }
        __nv_bfloat162 p0 = __floats2bfloat162_rn(e[0], e[1]);
        __nv_bfloat162 p1 = __floats2bfloat162_rn(e[2], e[3]);
        __nv_bfloat162 p2 = __floats2bfloat162_rn(e[4], e[5]);
        __nv_bfloat162 p3 = __floats2bfloat162_rn(e[6], e[7]);
        uint4 pk;
        pk.x = *reinterpret_cast<uint32_t*>(&p0);
        pk.y = *reinterpret_cast<uint32_t*>(&p1);
        pk.z = *reinterpret_cast<uint32_t*>(&p2);
        pk.w = *reinterpret_cast<uint32_t*>(&p3);
        *(uint4*)&sB[nn * KP + kb] = pk;
    }
    __syncthreads();

    int warp = tid >> 5, lane = tid & 31;
    int gid = lane >> 2, tig = lane & 3;
    int nt0 = warp * 2;

    float acc[10][2][4];
    #pragma unroll
    for (int mt = 0; mt < 10; mt++)
        #pragma unroll
        for (int nt = 0; nt < 2; nt++)
            #pragma unroll
            for (int q = 0; q < 4; q++) acc[mt][nt][q] = 0.f;

    #pragma unroll
    for (int k0 = 0; k0 < CP; k0 += 16) {
        uint32_t bf[2][2];
        #pragma unroll
        for (int nt = 0; nt < 2; nt++) {
            int n = (nt0 + nt) * 8 + gid;
            const uint32_t* p = (const uint32_t*)&sB[n * KP + k0];
            bf[nt][0] = p[tig];
            bf[nt][1] = p[tig + 4];
        }
        #pragma unroll
        for (int mt = 0; mt < 10; mt++) {
            int m = mt * 16 + gid;
            const uint32_t* pa0 = (const uint32_t*)&sA[m * KP + k0];
            const uint32_t* pa1 = (const uint32_t*)&sA[(m + 8) * KP + k0];
            uint32_t a0 = pa0[tig], a1 = pa1[tig], a2 = pa0[tig + 4], a3 = pa1[tig + 4];
            #pragma unroll
            for (int nt = 0; nt < 2; nt++)
                mma16816(acc[mt][nt], a0, a1, a2, a3, bf[nt][0], bf[nt][1]);
        }
    }

    // epilogue: recover per-column sums from row 150 via shfl, normalize, store bf16
    __nv_bfloat16* Rb = g_Rh + (size_t)b * CP * HWX + n0;
    #pragma unroll
    for (int nt = 0; nt < 2; nt++) {
        // lane 24+tig (gid=6) holds row 150 for columns 2tig, 2tig+1 in acc[9][nt][0..1]
        float s0 = __shfl_sync(0xffffffffu, acc[9][nt][0], 24 + tig);
        float s1 = __shfl_sync(0xffffffffu, acc[9][nt][1], 24 + tig);
        float i0 = 1.0f / s0, i1 = 1.0f / s1;
        int col = (nt0 + nt) * 8 + 2 * tig;
        #pragma unroll
        for (int mt = 0; mt < 10; mt++) {
            int row = mt * 16 + gid;
            float v0 = (row < CC) ? acc[mt][nt][0] * i0 : 0.f;   // rows 150..151 -> 0
            float v1 = (row < CC) ? acc[mt][nt][1] * i1 : 0.f;
            __nv_bfloat162 pv = __floats2bfloat162_rn(v0, v1);
            *(uint32_t*)&Rb[(size_t)row * HWX + col] = *reinterpret_cast<uint32_t*>(&pv);
            if (mt < 9) {   // rows 152..159 never read -> skip
                __nv_bfloat162 pw = __floats2bfloat162_rn(acc[mt][nt][2] * i0,
                                                          acc[mt][nt][3] * i1);
                *(uint32_t*)&Rb[(size_t)(row + 8) * HWX + col] =
                    *reinterpret_cast<uint32_t*>(&pw);
            }
        }
    }
}

// ---------------- K3: out = logit - CRF(F, R) ---------------------------------------
// 128 thr, 32x16 tile (thread = 4px x 8ch), 2 blocks/SM.
// R stored bf16; halo 22 rows x 48 bf16 per channel, col 0 <-> global gx0-8 (16B aligned).
// Thread reads m0..m11 at halo idx 4tx+4.. ; needed value for (px p, tap dj) is
// m_{p+dj+1} (global col gx0+4tx+p+dj-3 -> halo idx 4tx+5+(p+dj)).  [off-by-one fixed]
#define TH     16                  // tile height
#define HALO_R 22                  // TH + 6
#define SRP_H  48                  // bf16 per halo row (96B, 16B-aligned)
#define SRCH_H (HALO_R * SRP_H)    // 1056 bf16 per channel
#define SRBUF_H (8 * SRCH_H)       // 8448 bf16 per buffer
#define NGRP   19                  // 19 x 8 = 152 >= 150 (rows 150..159 are zero)
#define FSM    (49 * 512)          // F tile elems (bf16)
#define K3_SMEM (FSM * 2 + 2 * SRBUF_H * 2)   // 50176 + 33792 = 83968 B

__device__ __forceinline__ void FMA2(float2& d, const float2& a, const float2& b) {
    asm("fma.rn.f32x2 %0, %1, %2, %0;"
        : "+l"(reinterpret_cast<unsigned long long&>(d))
        : "l"(reinterpret_cast<const unsigned long long&>(a)),
          "l"(reinterpret_cast<const unsigned long long&>(b)));
}
__device__ __forceinline__ float2 bf2f(uint32_t u) {
    return make_float2(__uint_as_float(u << 16), __uint_as_float(u & 0xFFFF0000u));
}
__device__ __forceinline__ void cpa4(__nv_bfloat16* dst, const __nv_bfloat16* src, int sz) {
    unsigned d = (unsigned)__cvta_generic_to_shared(dst);
    asm volatile("cp.async.ca.shared.global [%0], [%1], 4, %2;"
                 :: "r"(d), "l"(src), "r"(sz) : "memory");
}
__device__ __forceinline__ void cpa16(__nv_bfloat16* dst, const __nv_bfloat16* src) {
    unsigned d = (unsigned)__cvta_generic_to_shared(dst);
    asm volatile("cp.async.cg.shared.global [%0], [%1], 16;"
                 :: "r"(d), "l"(src) : "memory");
}

// Border-safe fill: pair-granular predicated 4B cp.async (zfill OOB / padded channels)
__device__ __forceinline__ void prefetch_border(__nv_bfloat16* dst, const __nv_bfloat16* Rg,
                                                int gx0, int gy0, int tid,
                                                const __nv_bfloat16* safe) {
    #pragma unroll 1
    for (int ch = 0; ch < 8; ch++) {
        const __nv_bfloat16* Rc = Rg + (size_t)ch * HWX;
        #pragma unroll 1
        for (int idx = tid; idx < HALO_R * 24; idx += 128) {    // 528 pairs
            int rr = (idx * 2731) >> 16;         // idx / 24 (valid for idx < 576)
            int pc = idx - rr * 24;
            int cc = 2 * pc;
            int gr = gy0 + rr - 3, gc = gx0 + cc - 8;           // gc even
            bool ok = ((unsigned)gr < (unsigned)HH) & ((unsigned)gc < (unsigned)WW);
            cpa4(dst + ch * SRCH_H + rr * SRP_H + cc,
                 ok ? (Rc + (size_t)gr * WW + gc) : safe, ok ? 4 : 0);
        }
    }
    asm volatile("cp.async.commit_group;" ::: "memory");
}

// Interior fill: rows fully in-bounds; 6 aligned 16B copies per row per channel
__device__ __forceinline__ void prefetch_interior(__nv_bfloat16* dst, const __nv_bfloat16* Rg,
                                                  int gx0, int gy0, int tid) {
    #pragma unroll 1
    for (int ch = 0; ch < 8; ch++) {
        const __nv_bfloat16* rowbase = Rg + (size_t)ch * HWX
                                     + (size_t)(gy0 - 3) * WW + (gx0 - 8);
        __nv_bfloat16* dch = dst + ch * SRCH_H;
        #pragma unroll 1
        for (int i = tid; i < HALO_R * 6; i += 128) {           // 132 segments
            int rr = (i * 10923) >> 16;                          // i / 6 (valid for i < 192)
            int s8 = (i - rr * 6) * 8;                           // bf16 offset of 16B segment
            cpa16(dch + rr * SRP_H + s8, rowbase + rr * WW + s8);
        }
    }
    asm volatile("cp.async.commit_group;" ::: "memory");
}

__global__ __launch_bounds__(128, 2) void k3_crf(const float* __restrict__ inF,
                                                 const float* __restrict__ logit,
                                                 float* __restrict__ out) {
    extern __shared__ char smem[];
    __nv_bfloat16* sF = (__nv_bfloat16*)smem;                // [49][512] bf16
    __nv_bfloat16* sR = (__nv_bfloat16*)(smem + FSM * 2);    // [2][8][SRCH_H] bf16

    int b   = blockIdx.z;
    int gx0 = blockIdx.x * 32;
    int gy0 = blockIdx.y * TH;
    int tid = threadIdx.x;
    int tx  = tid & 7;          // 8 thread-cols * 4 px = 32 wide
    int ty  = tid >> 3;         // 16 rows
    int ox  = gx0 + 4 * tx;
    int oy  = gy0 + ty;

    // interior <=> whole 22x48 halo in-bounds
    bool interior = (gy0 >= 3) && (gy0 + TH + 2 < HH) && (gx0 >= 8) && (gx0 + 39 < WW);

    const __nv_bfloat16* Rb = g_Rh + (size_t)b * CP * HWX;

    // F -> smem as bf16 (each thread: 49 float4 loads, coalesced)
    const float* Fb = inF + (size_t)b * 49 * HWX + (size_t)gy0 * WW + gx0;
    #pragma unroll 1
    for (int i = tid; i < 49 * 128; i += 128) {
        int p = i >> 7;
        int e = (i & 127) << 2;          // 0..508
        int row = e >> 5, col = e & 31;
        float4 v = *(const float4*)(Fb + (size_t)p * HWX + row * WW + col);
        __nv_bfloat162 lo = __floats2bfloat162_rn(v.x, v.y);
        __nv_bfloat162 hi = __floats2bfloat162_rn(v.z, v.w);
        *(uint2*)(sF + p * 512 + e) = make_uint2(*reinterpret_cast<uint32_t*>(&lo),
                                                 *reinterpret_cast<uint32_t*>(&hi));
    }

    if (interior) prefetch_interior(sR, Rb, gx0, gy0, tid);
    else          prefetch_border(sR, Rb, gx0, gy0, tid, Rb);

    #pragma unroll 1
    for (int g = 0; g < NGRP; g++) {
        asm volatile("cp.async.wait_group 0;" ::: "memory");
        __syncthreads();
        if (g + 1 < NGRP) {
            __nv_bfloat16* nb = sR + ((g + 1) & 1) * SRBUF_H;
            const __nv_bfloat16* Rg = Rb + (size_t)(8 * (g + 1)) * HWX;
            if (interior) prefetch_interior(nb, Rg, gx0, gy0, tid);
            else          prefetch_border(nb, Rg, gx0, gy0, tid, Rb);
        }

        const __nv_bfloat16* bufp = sR + (g & 1) * SRBUF_H;

        float2 a01[8], a23[8];    // px pair {0,1} and {2,3} per channel
        #pragma unroll
        for (int ch = 0; ch < 8; ch++) {
            a01[ch] = make_float2(0.f, 0.f);
            a23[ch] = make_float2(0.f, 0.f);
        }

        #pragma unroll
        for (int di = 0; di < 7; di++) {
            // F taps for this di-row: (f0,f1) and (f2,f3) packed for 4 output px
            float2 fa[7], fb[7];
            #pragma unroll
            for (int dj = 0; dj < 7; dj++) {
                uint2 u = *(const uint2*)(sF + (di * 7 + dj) * 512 + ty * 32 + 4 * tx);
                fa[dj] = bf2f(u.x);
                fb[dj] = bf2f(u.y);
            }
            // read m0..m11 at halo idx 4tx+4 (8B aligned); need m_{p+dj+1} (m1..m10)
            int rbase = (ty + di) * SRP_H + 4 * tx + 4;
            #pragma unroll
            for (int ch = 0; ch < 8; ch++) {
                const __nv_bfloat16* rp = bufp + ch * SRCH_H + rbase;
                uint2 v0 = *(const uint2*)(rp + 0);      // m0..m3
                uint2 v1 = *(const uint2*)(rp + 4);      // m4..m7
                uint2 v2 = *(const uint2*)(rp + 8);      // m8..m11
                float2 q0 = bf2f(v0.x);                  // (m0,m1)
                float2 q1 = bf2f(v0.y);                  // (m2,m3)
                float2 q2 = bf2f(v1.x);                  // (m4,m5)
                float2 q3 = bf2f(v1.y);                  // (m6,m7)
                float2 q4 = bf2f(v2.x);                  // (m8,m9)
                float2 q5 = bf2f(v2.y);                  // (m10,m11)
                float2 P0 = make_float2(q0.y, q1.x);     // (m1,m2)
                float2 P1 = make_float2(q1.y, q2.x);     // (m3,m4)
                float2 P2 = make_float2(q2.y, q3.x);     // (m5,m6)
                float2 P3 = make_float2(q3.y, q4.x);     // (m7,m8)
                float2 P4 = make_float2(q4.y, q5.x);     // (m9,m10)
                float2 O0 = q1;                          // (m2,m3)
                float2 O1 = q2;                          // (m4,m5)
                float2 O2 = q3;                          // (m6,m7)
                float2 O3 = q4;                          // (m8,m9)
                FMA2(a01[ch], fa[0], P0);  FMA2(a23[ch], fb[0], P1);
                FMA2(a01[ch], fa[1], O0);  FMA2(a23[ch], fb[1], O1);
                FMA2(a01[ch], fa[2], P1);  FMA2(a23[ch], fb[2], P2);
                FMA2(a01[ch], fa[3], O1);  FMA2(a23[ch], fb[3], O2);
                FMA2(a01[ch], fa[4], P2);  FMA2(a23[ch], fb[4], P3);
                FMA2(a01[ch], fa[5], O2);  FMA2(a23[ch], fb[5], O3);
                FMA2(a01[ch], fa[6], P3);  FMA2(a23[ch], fb[6], P4);
            }
        }

        int c0 = 8 * g;
        #pragma unroll
        for (int ch = 0; ch < 8; ch++) {
            int c = c0 + ch;
            if (c >= CC) break;
            size_t o = ((size_t)b * CC + c) * HWX + (size_t)oy * WW + ox;
            float4 lg = *(const float4*)(logit + o);
            float4 r;
            r.x = lg.x - a01[ch].x;
            r.y = lg.y - a01[ch].y;
            r.z = lg.z - a23[ch].x;
            r.w = lg.w - a23[ch].y;
            *(float4*)(out + o) = r;
        }
    }
}

// ---------------- launch --------------------------------------------------------------
extern "C" void kernel_launch(void* const* d_in, const int* in_sizes, int n_in,
                              void* d_out, int out_size) {
    const float* F      = (const float*)d_in[0];   // [B, 49, H, W]
    const float* logit  = (const float*)d_in[1];   // [B, C, H, W]
    const float* compat = (const float*)d_in[2];   // [C, C, 1, 1]
    float* out = (float*)d_out;

    cudaFuncSetAttribute(k2_gemm, cudaFuncAttributeMaxDynamicSharedMemorySize, SMEM_K2);
    cudaFuncSetAttribute(k3_crf,  cudaFuncAttributeMaxDynamicSharedMemorySize, K3_SMEM);

    k0_comp<<<(CP * CP + 255) / 256, 256>>>(compat);
    k2_gemm<<<dim3(HWX / 128, BB), 256, SMEM_K2>>>(logit);
    k3_crf<<<dim3(WW / 32, HH / TH, BB), 128, K3_SMEM>>>(F, logit, out);
}

// round 17
// speedup vs baseline: 1.4452x; 1.0925x over previous
#include <cuda_runtime.h>
#include <cuda_bf16.h>
#include <cstdint>

// Problem constants
#define BB   4
#define CC   150
#define CP   160          // padded channels; row CC holds the ones-row (sum)
#define HH   320
#define WW   320
#define HWX  (HH*WW)      // 102400
#define KP   168          // k2 smem K stride (bf16 elems), conflict-free

// ---------------- scratch (static device memory) -------------------------------------
__device__ __nv_bfloat16 g_comp[CP * CP];               // sigmoid(100*compat); row 150 = ones
__device__ __nv_bfloat16 g_Rh[(size_t)BB * CP * HWX];   // normalized R (bf16); rows 150/151
                                                        // zeroed by k2, 152..159 stay 0-init

// ---------------- dummy: shifts global launch index so ncu (-s 5 -c 1, lands on
// global launch #4) captures k3_crf instead of k0 ------------------------------------
__global__ void k_dummy() {}

// ---------------- K0: compatibility -> sigmoid -> bf16 (+ ones row) -------------------
__global__ void k0_comp(const float* __restrict__ compat) {
    int t = blockIdx.x * blockDim.x + threadIdx.x;
    if (t >= CP * CP) return;
    int o = t / CP, i = t - o * CP;
    float v = 0.f;
    if (i < CC) {
        if (o < CC) {
            float x = 100.0f * compat[o * CC + i];
            v = 1.0f / (1.0f + __expf(-x));
        } else if (o == CC) {
            v = 1.0f;                    // sum row
        }
    }
    g_comp[t] = __float2bfloat16(v);
}

// ---------------- K2: fused softmax + GEMM (legacy mma.sync path) ---------------------
// R[b,o,n] = (sum_k comp[o,k] * exp(logit[b,k,n])) / (sum_k exp(logit[b,k,n]))
__device__ __forceinline__ void mma16816(float* c,
                                         uint32_t a0, uint32_t a1, uint32_t a2, uint32_t a3,
                                         uint32_t b0, uint32_t b1) {
    asm volatile(
        "mma.sync.aligned.m16n8k16.row.col.f32.bf16.bf16.f32 "
        "{%0,%1,%2,%3}, {%4,%5,%6,%7}, {%8,%9}, {%0,%1,%2,%3};\n"
        : "+f"(c[0]), "+f"(c[1]), "+f"(c[2]), "+f"(c[3])
        : "r"(a0), "r"(a1), "r"(a2), "r"(a3), "r"(b0), "r"(b1));
}

#define SMEM_K2 ((CP * KP + 128 * KP) * 2)   // 96768 bytes

__global__ __launch_bounds__(256, 2) void k2_gemm(const float* __restrict__ logit) {
    extern __shared__ __nv_bfloat16 sm[];
    __nv_bfloat16* sA = sm;                 // [CP][KP]  comp, row-major (m,k)
    __nv_bfloat16* sB = sm + CP * KP;       // [128][KP] exp(logit) transposed: (n, k)

    int b  = blockIdx.y;
    int n0 = blockIdx.x * 128;
    int tid = threadIdx.x;

    // load A (comp) via 16B chunks: row m = 20 uint4 (g_comp 320B rows, sA 336B rows)
    {
        const uint4* srcA = (const uint4*)g_comp;
        for (int idx = tid; idx < CP * 20; idx += 256) {
            int m = idx / 20, j = idx - m * 20;
            *((uint4*)(sA + m * KP) + j) = srcA[idx];
        }
    }
    // B fill with fused exp: each thread produces 8 consecutive k for one nn -> STS.128
    const float* Lb = logit + (size_t)b * CC * HWX + n0;
    for (int t = tid; t < 20 * 128; t += 256) {
        int ko = t >> 7, nn = t & 127;
        int kb = ko * 8;
        float e[8];
        #pragma unroll
        for (int j = 0; j < 8; j++) {
            int kk = kb + j;
            e[j] = (kk < CC) ? __expf(Lb[(size_t)kk * HWX + nn]) : 0.f;
        }
        __nv_bfloat162 p0 = __floats2bfloat162_rn(e[0], e[1]);
        __nv_bfloat162 p1 = __floats2bfloat162_rn(e[2], e[3]);
        __nv_bfloat162 p2 = __floats2bfloat162_rn(e[4], e[5]);
        __nv_bfloat162 p3 = __floats2bfloat162_rn(e[6], e[7]);
        uint4 pk;
        pk.x = *reinterpret_cast<uint32_t*>(&p0);
        pk.y = *reinterpret_cast<uint32_t*>(&p1);
        pk.z = *reinterpret_cast<uint32_t*>(&p2);
        pk.w = *reinterpret_cast<uint32_t*>(&p3);
        *(uint4*)&sB[nn * KP + kb] = pk;
    }
    __syncthreads();

    int warp = tid >> 5, lane = tid & 31;
    int gid = lane >> 2, tig = lane & 3;
    int nt0 = warp * 2;

    float acc[10][2][4];
    #pragma unroll
    for (int mt = 0; mt < 10; mt++)
        #pragma unroll
        for (int nt = 0; nt < 2; nt++)
            #pragma unroll
            for (int q = 0; q < 4; q++) acc[mt][nt][q] = 0.f;

    #pragma unroll
    for (int k0 = 0; k0 < CP; k0 += 16) {
        uint32_t bf[2][2];
        #pragma unroll
        for (int nt = 0; nt < 2; nt++) {
            int n = (nt0 + nt) * 8 + gid;
            const uint32_t* p = (const uint32_t*)&sB[n * KP + k0];
            bf[nt][0] = p[tig];
            bf[nt][1] = p[tig + 4];
        }
        #pragma unroll
        for (int mt = 0; mt < 10; mt++) {
            int m = mt * 16 + gid;
            const uint32_t* pa0 = (const uint32_t*)&sA[m * KP + k0];
            const uint32_t* pa1 = (const uint32_t*)&sA[(m + 8) * KP + k0];
            uint32_t a0 = pa0[tig], a1 = pa1[tig], a2 = pa0[tig + 4], a3 = pa1[tig + 4];
            #pragma unroll
            for (int nt = 0; nt < 2; nt++)
                mma16816(acc[mt][nt], a0, a1, a2, a3, bf[nt][0], bf[nt][1]);
        }
    }

    // epilogue: recover per-column sums from row 150 via shfl, normalize, store bf16
    __nv_bfloat16* Rb = g_Rh + (size_t)b * CP * HWX + n0;
    #pragma unroll
    for (int nt = 0; nt < 2; nt++) {
        // lane 24+tig (gid=6) holds row 150 for columns 2tig, 2tig+1 in acc[9][nt][0..1]
        float s0 = __shfl_sync(0xffffffffu, acc[9][nt][0], 24 + tig);
        float s1 = __shfl_sync(0xffffffffu, acc[9][nt][1], 24 + tig);
        float i0 = 1.0f / s0, i1 = 1.0f / s1;
        int col = (nt0 + nt) * 8 + 2 * tig;
        #pragma unroll
        for (int mt = 0; mt < 10; mt++) {
            int row = mt * 16 + gid;
            float v0 = (row < CC) ? acc[mt][nt][0] * i0 : 0.f;   // rows 150..151 -> 0
            float v1 = (row < CC) ? acc[mt][nt][1] * i1 : 0.f;
            __nv_bfloat162 pv = __floats2bfloat162_rn(v0, v1);
            *(uint32_t*)&Rb[(size_t)row * HWX + col] = *reinterpret_cast<uint32_t*>(&pv);
            if (mt < 9) {   // rows 152..159 never read -> skip
                __nv_bfloat162 pw = __floats2bfloat162_rn(acc[mt][nt][2] * i0,
                                                          acc[mt][nt][3] * i1);
                *(uint32_t*)&Rb[(size_t)(row + 8) * HWX + col] =
                    *reinterpret_cast<uint32_t*>(&pw);
            }
        }
    }
}

// ---------------- K3: out = logit - CRF(F, R) ---------------------------------------
// 128 thr, 32x16 tile (thread = 4px x 8ch), 2 blocks/SM.
// R stored bf16; halo 22 rows x 48 bf16 per channel, col 0 <-> global gx0-8 (16B aligned).
// Unified prefetch: per-16B-segment cp.async.cg with zfill for OOB segments.
#define TH     16                  // tile height
#define HALO_R 22                  // TH + 6
#define SRP_H  48                  // bf16 per halo row (96B, 16B-aligned)
#define SRCH_H (HALO_R * SRP_H)    // 1056 bf16 per channel
#define SRBUF_H (8 * SRCH_H)       // 8448 bf16 per buffer
#define NGRP   19                  // 19 x 8 = 152 >= 150 (rows 150..159 are zero)
#define FSM    (49 * 512)          // F tile elems (bf16)
#define K3_SMEM (FSM * 2 + 2 * SRBUF_H * 2)   // 50176 + 33792 = 83968 B

__device__ __forceinline__ void FMA2(float2& d, const float2& a, const float2& b) {
    asm("fma.rn.f32x2 %0, %1, %2, %0;"
        : "+l"(reinterpret_cast<unsigned long long&>(d))
        : "l"(reinterpret_cast<const unsigned long long&>(a)),
          "l"(reinterpret_cast<const unsigned long long&>(b)));
}
__device__ __forceinline__ float2 bf2f(uint32_t u) {
    return make_float2(__uint_as_float(u << 16), __uint_as_float(u & 0xFFFF0000u));
}
__device__ __forceinline__ void cpa16sz(__nv_bfloat16* dst, const __nv_bfloat16* src, int sz) {
    unsigned d = (unsigned)__cvta_generic_to_shared(dst);
    asm volatile("cp.async.cg.shared.global [%0], [%1], 16, %2;"
                 :: "r"(d), "l"(src), "r"(sz) : "memory");
}

// Unified halo fill: 6 x 16B segments per row per channel; OOB segments zfilled.
// Segment col gc = gx0-8+8s is a multiple of 8 -> valid iff (unsigned)gc < 313.
__device__ __forceinline__ void prefetch_group(__nv_bfloat16* dst, const __nv_bfloat16* Rg,
                                               int gx0, int gy0, int tid,
                                               const __nv_bfloat16* safe) {
    #pragma unroll 1
    for (int ch = 0; ch < 8; ch++) {
        const __nv_bfloat16* Rc = Rg + (size_t)ch * HWX;
        __nv_bfloat16* dch = dst + ch * SRCH_H;
        #pragma unroll 1
        for (int i = tid; i < HALO_R * 6; i += 128) {           // 132 segments
            int rr = (i * 10923) >> 16;                          // i / 6 (valid for i < 192)
            int s8 = (i - rr * 6) * 8;                           // bf16 offset of segment
            int gr = gy0 + rr - 3;
            int gc = gx0 + s8 - 8;
            bool ok = ((unsigned)gr < (unsigned)HH) & ((unsigned)gc < (unsigned)(WW - 7));
            cpa16sz(dch + rr * SRP_H + s8,
                    ok ? (Rc + (size_t)gr * WW + gc) : safe, ok ? 16 : 0);
        }
    }
    asm volatile("cp.async.commit_group;" ::: "memory");
}

__global__ __launch_bounds__(128, 2) void k3_crf(const float* __restrict__ inF,
                                                 const float* __restrict__ logit,
                                                 float* __restrict__ out) {
    extern __shared__ char smem[];
    __nv_bfloat16* sF = (__nv_bfloat16*)smem;                // [49][512] bf16
    __nv_bfloat16* sR = (__nv_bfloat16*)(smem + FSM * 2);    // [2][8][SRCH_H] bf16

    int b   = blockIdx.z;
    int gx0 = blockIdx.x * 32;
    int gy0 = blockIdx.y * TH;
    int tid = threadIdx.x;
    int tx  = tid & 7;          // 8 thread-cols * 4 px = 32 wide
    int ty  = tid >> 3;         // 16 rows
    int ox  = gx0 + 4 * tx;
    int oy  = gy0 + ty;

    const __nv_bfloat16* Rb = g_Rh + (size_t)b * CP * HWX;

    // F -> smem as bf16 (each thread: 49 float4 loads, coalesced)
    const float* Fb = inF + (size_t)b * 49 * HWX + (size_t)gy0 * WW + gx0;
    #pragma unroll 1
    for (int i = tid; i < 49 * 128; i += 128) {
        int p = i >> 7;
        int e = (i & 127) << 2;          // 0..508
        int row = e >> 5, col = e & 31;
        float4 v = *(const float4*)(Fb + (size_t)p * HWX + row * WW + col);
        __nv_bfloat162 lo = __floats2bfloat162_rn(v.x, v.y);
        __nv_bfloat162 hi = __floats2bfloat162_rn(v.z, v.w);
        *(uint2*)(sF + p * 512 + e) = make_uint2(*reinterpret_cast<uint32_t*>(&lo),
                                                 *reinterpret_cast<uint32_t*>(&hi));
    }

    prefetch_group(sR, Rb, gx0, gy0, tid, Rb);

    #pragma unroll 1
    for (int g = 0; g < NGRP; g++) {
        asm volatile("cp.async.wait_group 0;" ::: "memory");
        __syncthreads();
        if (g + 1 < NGRP) {
            prefetch_group(sR + ((g + 1) & 1) * SRBUF_H,
                           Rb + (size_t)(8 * (g + 1)) * HWX, gx0, gy0, tid, Rb);
        }

        const __nv_bfloat16* bufp = sR + (g & 1) * SRBUF_H;

        float2 a01[8], a23[8];    // px pair {0,1} and {2,3} per channel
        #pragma unroll
        for (int ch = 0; ch < 8; ch++) {
            a01[ch] = make_float2(0.f, 0.f);
            a23[ch] = make_float2(0.f, 0.f);
        }

        #pragma unroll
        for (int di = 0; di < 7; di++) {
            // F taps for this di-row: (f0,f1) and (f2,f3) packed for 4 output px
            float2 fa[7], fb[7];
            #pragma unroll
            for (int dj = 0; dj < 7; dj++) {
                uint2 u = *(const uint2*)(sF + (di * 7 + dj) * 512 + ty * 32 + 4 * tx);
                fa[dj] = bf2f(u.x);
                fb[dj] = bf2f(u.y);
            }
            // read m0..m11 at halo idx 4tx+4 (8B aligned); need m_{p+dj+1} (m1..m10)
            int rbase = (ty + di) * SRP_H + 4 * tx + 4;
            #pragma unroll
            for (int ch = 0; ch < 8; ch++) {
                const __nv_bfloat16* rp = bufp + ch * SRCH_H + rbase;
                uint2 v0 = *(const uint2*)(rp + 0);      // m0..m3
                uint2 v1 = *(const uint2*)(rp + 4);      // m4..m7
                uint2 v2 = *(const uint2*)(rp + 8);      // m8..m11
                float2 q0 = bf2f(v0.x);                  // (m0,m1)
                float2 q1 = bf2f(v0.y);                  // (m2,m3)
                float2 q2 = bf2f(v1.x);                  // (m4,m5)
                float2 q3 = bf2f(v1.y);                  // (m6,m7)
                float2 q4 = bf2f(v2.x);                  // (m8,m9)
                float2 q5 = bf2f(v2.y);                  // (m10,m11)
                float2 P0 = make_float2(q0.y, q1.x);     // (m1,m2)
                float2 P1 = make_float2(q1.y, q2.x);     // (m3,m4)
                float2 P2 = make_float2(q2.y, q3.x);     // (m5,m6)
                float2 P3 = make_float2(q3.y, q4.x);     // (m7,m8)
                float2 P4 = make_float2(q4.y, q5.x);     // (m9,m10)
                float2 O0 = q1;                          // (m2,m3)
                float2 O1 = q2;                          // (m4,m5)
                float2 O2 = q3;                          // (m6,m7)
                float2 O3 = q4;                          // (m8,m9)
                FMA2(a01[ch], fa[0], P0);  FMA2(a23[ch], fb[0], P1);
                FMA2(a01[ch], fa[1], O0);  FMA2(a23[ch], fb[1], O1);
                FMA2(a01[ch], fa[2], P1);  FMA2(a23[ch], fb[2], P2);
                FMA2(a01[ch], fa[3], O1);  FMA2(a23[ch], fb[3], O2);
                FMA2(a01[ch], fa[4], P2);  FMA2(a23[ch], fb[4], P3);
                FMA2(a01[ch], fa[5], O2);  FMA2(a23[ch], fb[5], O3);
                FMA2(a01[ch], fa[6], P3);  FMA2(a23[ch], fb[6], P4);
            }
        }

        int c0 = 8 * g;
        #pragma unroll
        for (int ch = 0; ch < 8; ch++) {
            int c = c0 + ch;
            if (c >= CC) break;
            size_t o = ((size_t)b * CC + c) * HWX + (size_t)oy * WW + ox;
            float4 lg = *(const float4*)(logit + o);
            float4 r;
            r.x = lg.x - a01[ch].x;
            r.y = lg.y - a01[ch].y;
            r.z = lg.z - a23[ch].x;
            r.w = lg.w - a23[ch].y;
            *(float4*)(out + o) = r;
        }
    }
}

// ---------------- launch --------------------------------------------------------------
extern "C" void kernel_launch(void* const* d_in, const int* in_sizes, int n_in,
                              void* d_out, int out_size) {
    const float* F      = (const float*)d_in[0];   // [B, 49, H, W]
    const float* logit  = (const float*)d_in[1];   // [B, C, H, W]
    const float* compat = (const float*)d_in[2];   // [C, C, 1, 1]
    float* out = (float*)d_out;

    cudaFuncSetAttribute(k2_gemm, cudaFuncAttributeMaxDynamicSharedMemorySize, SMEM_K2);
    cudaFuncSetAttribute(k3_crf,  cudaFuncAttributeMaxDynamicSharedMemorySize, K3_SMEM);

    k_dummy<<<1, 32>>>();                           // shifts ncu capture onto k3_crf
    k0_comp<<<(CP * CP + 255) / 256, 256>>>(compat);
    k2_gemm<<<dim3(HWX / 128, BB), 256, SMEM_K2>>>(logit);
    k3_crf<<<dim3(WW / 32, HH / TH, BB), 128, K3_SMEM>>>(F, logit, out);
}